// round 5
// baseline (speedup 1.0000x reference)
#include <cuda_runtime.h>
#include <cstdint>

// Problem constants
#define NB    4
#define TSEQ  4096
#define CDIM  1024
#define HDIM  64
#define MROWS (NB * TSEQ)   // 16384

// Scratch for projected q, k, v  (12 MB total) — __device__ globals per alloc rules
__device__ float g_q[MROWS * HDIM];
__device__ float g_k[MROWS * HDIM];
__device__ float g_v[MROWS * HDIM];

// qb permutation: colocated wave-1 CTA pairs are (bid, bid+148) -> bx pairs
// (x, (x+20) mod 64). Table built on the 4 cycles of +20 mod 64, alternating
// low/high values so every colocated pair sums to 63 or 67 (near-flat SM load).
__constant__ int c_qbtab[64] = {
     0,  1,  2,  3, 39, 38, 37, 36, 20, 21, 22, 23, 51, 50, 49, 48,
     8,  9, 10, 11, 63, 62, 61, 60, 28, 29, 30, 31, 43, 42, 41, 40,
    16, 17, 18, 19, 55, 54, 53, 52,  4,  5,  6,  7, 35, 34, 33, 32,
    24, 25, 26, 27, 47, 46, 45, 44, 12, 13, 14, 15, 59, 58, 57, 56
};

// ---------------------------------------------------------------------------
// Projection: out[m][h] = sum_c x[m][c] * W[h][c]
// (measured ~177us, near the fp32 FFMA floor ~190us — unchanged this round)
// ---------------------------------------------------------------------------
#define PJ_STR 36   // 32 + 4 pad (144B rows, 16B-aligned)

__global__ __launch_bounds__(256) void proj_kernel(
    const float* __restrict__ x,
    const float* __restrict__ Wq,
    const float* __restrict__ Wk,
    const float* __restrict__ Wv)
{
    __shared__ float As[64 * PJ_STR];  // x tile   [m][c]
    __shared__ float Bs[64 * PJ_STR];  // W tile   [n][c]

    const int wsel = blockIdx.y;
    const float* __restrict__ W = (wsel == 0) ? Wq : ((wsel == 1) ? Wk : Wv);
    float* __restrict__ dst     = (wsel == 0) ? g_q : ((wsel == 1) ? g_k : g_v);

    const int m0 = blockIdx.x * 64;
    const int t  = threadIdx.x;
    const int tx = t & 15;
    const int ty = t >> 4;

    float acc[4][4] = {};

    for (int kb = 0; kb < CDIM; kb += 32) {
        #pragma unroll
        for (int p = 0; p < 2; p++) {
            const int f   = t + p * 256;
            const int row = f >> 3;
            const int c   = (f & 7) * 4;
            *(float4*)(As + row * PJ_STR + c) =
                *(const float4*)(x + (m0 + row) * CDIM + kb + c);
            *(float4*)(Bs + row * PJ_STR + c) =
                *(const float4*)(W + row * CDIM + kb + c);
        }
        __syncthreads();

        #pragma unroll
        for (int kk = 0; kk < 32; kk += 4) {
            float4 av[4], bv[4];
            #pragma unroll
            for (int ii = 0; ii < 4; ii++)
                av[ii] = *(const float4*)(As + (ty + 16 * ii) * PJ_STR + kk);
            #pragma unroll
            for (int jj = 0; jj < 4; jj++)
                bv[jj] = *(const float4*)(Bs + (tx + 16 * jj) * PJ_STR + kk);
            #pragma unroll
            for (int ii = 0; ii < 4; ii++)
                #pragma unroll
                for (int jj = 0; jj < 4; jj++) {
                    acc[ii][jj] = fmaf(av[ii].x, bv[jj].x, acc[ii][jj]);
                    acc[ii][jj] = fmaf(av[ii].y, bv[jj].y, acc[ii][jj]);
                    acc[ii][jj] = fmaf(av[ii].z, bv[jj].z, acc[ii][jj]);
                    acc[ii][jj] = fmaf(av[ii].w, bv[jj].w, acc[ii][jj]);
                }
        }
        __syncthreads();
    }

    #pragma unroll
    for (int ii = 0; ii < 4; ii++)
        #pragma unroll
        for (int jj = 0; jj < 4; jj++)
            dst[(m0 + ty + 16 * ii) * HDIM + (tx + 16 * jj)] = acc[ii][jj];
}

// ---------------------------------------------------------------------------
// Flash attention (fp32, causal). grid = (64, 4) = 256 CTAs, 256 thr,
// 2 CTAs/SM (69632B smem x2 < 228KB) -> ALL CTAs resident in one wave.
// qb from c_qbtab balances colocated-pair load. Single-buffered K/V,
// 3 barriers/iter. Online softmax register-resident (16-lane shuffles).
// P staged in permuted layout St[j][ty*4+ii] -> PV reads P as one LDS.128.
// Smem (floats, stride 68 = 272B rows, 16B aligned):
//   Qs [64][68]  Ks [64][68]  Vs [64][68]  St [64][68]
// ---------------------------------------------------------------------------
#define AT_STR  68
#define SM_QS   0
#define SM_KS   (64 * AT_STR)
#define SM_VS   (2 * 64 * AT_STR)
#define SM_ST   (3 * 64 * AT_STR)
#define SM_TOTF (4 * 64 * AT_STR)           // 17408 floats
#define ATTN_SMEM_BYTES (SM_TOTF * 4)       // 69632 bytes

__global__ __launch_bounds__(256, 2) void attn_kernel(float* __restrict__ out)
{
    extern __shared__ float sm[];
    float* Qs = sm + SM_QS;
    float* Ks = sm + SM_KS;
    float* Vs = sm + SM_VS;
    float* St = sm + SM_ST;

    const int t  = threadIdx.x;
    const int tx = t & 15;
    const int ty = t >> 4;
    const int qb = c_qbtab[blockIdx.x];
    const int b  = blockIdx.y;
    const float NEGBIG = -1e30f;
    const float scale  = 0.125f;          // 64^-0.5

    // cooperative tile-load map (4 float4 per thread)
    const int lrow0 = t >> 4;             // +16 per p
    const int lcol  = (t & 15) * 4;

    const float* __restrict__ kbase = g_k + b * TSEQ * HDIM;
    const float* __restrict__ vbase = g_v + b * TSEQ * HDIM;

    // ---- load Q tile (pre-scaled) ----
    {
        const float* __restrict__ qsrc = g_q + (b * TSEQ + qb * 64) * HDIM;
        #pragma unroll
        for (int p = 0; p < 4; p++) {
            const int row = lrow0 + p * 16;
            float4 q4 = *(const float4*)(qsrc + row * HDIM + lcol);
            q4.x *= scale; q4.y *= scale; q4.z *= scale; q4.w *= scale;
            *(float4*)(Qs + row * AT_STR + lcol) = q4;
        }
    }

    float m_i[4], l_i[4];
    #pragma unroll
    for (int ii = 0; ii < 4; ii++) { m_i[ii] = NEGBIG; l_i[ii] = 0.0f; }
    float o[4][4] = {};   // rows ty+16*ii, cols tx*4+jj

    for (int jt = 0; jt <= qb; jt++) {
        // ---- load K and V tiles (single buffer) ----
        {
            const float* __restrict__ ksrc = kbase + jt * 64 * HDIM;
            const float* __restrict__ vsrc = vbase + jt * 64 * HDIM;
            #pragma unroll
            for (int p = 0; p < 4; p++) {
                const int row = lrow0 + p * 16;
                *(float4*)(Ks + row * AT_STR + lcol) =
                    *(const float4*)(ksrc + row * HDIM + lcol);
                *(float4*)(Vs + row * AT_STR + lcol) =
                    *(const float4*)(vsrc + row * HDIM + lcol);
            }
        }
        __syncthreads();                               // barrier 1: tiles ready

        // ---- S = (Q*scale) @ K^T ----
        float s[4][4] = {};
        #pragma unroll
        for (int kk = 0; kk < 64; kk += 4) {
            float4 av[4], bv[4];
            #pragma unroll
            for (int ii = 0; ii < 4; ii++)
                av[ii] = *(const float4*)(Qs + (ty + 16 * ii) * AT_STR + kk);
            #pragma unroll
            for (int jj = 0; jj < 4; jj++)
                bv[jj] = *(const float4*)(Ks + (tx + 16 * jj) * AT_STR + kk);
            #pragma unroll
            for (int ii = 0; ii < 4; ii++)
                #pragma unroll
                for (int jj = 0; jj < 4; jj++) {
                    s[ii][jj] = fmaf(av[ii].x, bv[jj].x, s[ii][jj]);
                    s[ii][jj] = fmaf(av[ii].y, bv[jj].y, s[ii][jj]);
                    s[ii][jj] = fmaf(av[ii].z, bv[jj].z, s[ii][jj]);
                    s[ii][jj] = fmaf(av[ii].w, bv[jj].w, s[ii][jj]);
                }
        }

        // causal mask on the diagonal tile
        if (jt == qb) {
            #pragma unroll
            for (int ii = 0; ii < 4; ii++)
                #pragma unroll
                for (int jj = 0; jj < 4; jj++)
                    if ((tx + 16 * jj) > (ty + 16 * ii)) s[ii][jj] = NEGBIG;
        }

        // ---- online softmax (register-resident, 16-lane shuffle trees) ----
        float alpha[4];
        #pragma unroll
        for (int ii = 0; ii < 4; ii++) {
            float tm = fmaxf(fmaxf(s[ii][0], s[ii][1]),
                             fmaxf(s[ii][2], s[ii][3]));
            #pragma unroll
            for (int w = 1; w < 16; w <<= 1)
                tm = fmaxf(tm, __shfl_xor_sync(0xffffffffu, tm, w));
            const float mnew = fmaxf(m_i[ii], tm);
            alpha[ii] = __expf(m_i[ii] - mnew);
            m_i[ii]   = mnew;
        }

        // P = exp(S-m); row sums via shuffle; stage P in permuted layout:
        // St[j][ty*4 + ii]  (so PV reads a thread's 4 P values as one float4)
        #pragma unroll
        for (int ii = 0; ii < 4; ii++) {
            float p0 = __expf(s[ii][0] - m_i[ii]);
            float p1 = __expf(s[ii][1] - m_i[ii]);
            float p2 = __expf(s[ii][2] - m_i[ii]);
            float p3 = __expf(s[ii][3] - m_i[ii]);
            float rs = (p0 + p1) + (p2 + p3);
            #pragma unroll
            for (int w = 1; w < 16; w <<= 1)
                rs += __shfl_xor_sync(0xffffffffu, rs, w);
            l_i[ii] = l_i[ii] * alpha[ii] + rs;
            o[ii][0] *= alpha[ii]; o[ii][1] *= alpha[ii];
            o[ii][2] *= alpha[ii]; o[ii][3] *= alpha[ii];
            const int pc = ty * 4 + ii;
            St[(tx +  0) * AT_STR + pc] = p0;
            St[(tx + 16) * AT_STR + pc] = p1;
            St[(tx + 32) * AT_STR + pc] = p2;
            St[(tx + 48) * AT_STR + pc] = p3;
        }
        __syncthreads();                               // barrier 2: St ready

        // ---- O += P @ V : both operands as LDS.128 ----
        #pragma unroll 8
        for (int j = 0; j < 64; j++) {
            const float4 pv = *(const float4*)(St + j * AT_STR + ty * 4);
            const float4 vv = *(const float4*)(Vs + j * AT_STR + tx * 4);
            o[0][0] = fmaf(pv.x, vv.x, o[0][0]);
            o[0][1] = fmaf(pv.x, vv.y, o[0][1]);
            o[0][2] = fmaf(pv.x, vv.z, o[0][2]);
            o[0][3] = fmaf(pv.x, vv.w, o[0][3]);
            o[1][0] = fmaf(pv.y, vv.x, o[1][0]);
            o[1][1] = fmaf(pv.y, vv.y, o[1][1]);
            o[1][2] = fmaf(pv.y, vv.z, o[1][2]);
            o[1][3] = fmaf(pv.y, vv.w, o[1][3]);
            o[2][0] = fmaf(pv.z, vv.x, o[2][0]);
            o[2][1] = fmaf(pv.z, vv.y, o[2][1]);
            o[2][2] = fmaf(pv.z, vv.z, o[2][2]);
            o[2][3] = fmaf(pv.z, vv.w, o[2][3]);
            o[3][0] = fmaf(pv.w, vv.x, o[3][0]);
            o[3][1] = fmaf(pv.w, vv.y, o[3][1]);
            o[3][2] = fmaf(pv.w, vv.z, o[3][2]);
            o[3][3] = fmaf(pv.w, vv.w, o[3][3]);
        }
        __syncthreads();                               // barrier 3: bufs safe
    }

    // ---- epilogue: out = O / l ----
    #pragma unroll
    for (int ii = 0; ii < 4; ii++) {
        const int i     = ty + 16 * ii;
        const float inv = 1.0f / l_i[ii];
        float4 ov;
        ov.x = o[ii][0] * inv; ov.y = o[ii][1] * inv;
        ov.z = o[ii][2] * inv; ov.w = o[ii][3] * inv;
        *(float4*)(out + (b * TSEQ + qb * 64 + i) * HDIM + tx * 4) = ov;
    }
}

// ---------------------------------------------------------------------------
// kernel_launch — inputs (metadata order): x, mask(int32, unused), Wk, Wq, Wv
// ---------------------------------------------------------------------------
extern "C" void kernel_launch(void* const* d_in, const int* in_sizes, int n_in,
                              void* d_out, int out_size)
{
    const float* x  = (const float*)d_in[0];
    // d_in[1] = mask (int32) — causality is known; not read.
    const float* Wk = (const float*)d_in[2];
    const float* Wq = (const float*)d_in[3];
    const float* Wv = (const float*)d_in[4];
    float* out = (float*)d_out;

    // Host-side attribute set; not a stream op, safe under graph capture.
    cudaFuncSetAttribute(attn_kernel,
                         cudaFuncAttributeMaxDynamicSharedMemorySize,
                         ATTN_SMEM_BYTES);

    dim3 pgrid(MROWS / 64, 3);
    proj_kernel<<<pgrid, 256>>>(x, Wq, Wk, Wv);

    dim3 agrid(64, NB);   // one wave: 256 CTAs <= 148 SMs x 2
    attn_kernel<<<agrid, 256, ATTN_SMEM_BYTES>>>(out);
}

// round 8
// speedup vs baseline: 1.3614x; 1.3614x over previous
#include <cuda_runtime.h>
#include <cstdint>

// Problem constants
#define NB    4
#define TSEQ  4096
#define CDIM  1024
#define HDIM  64
#define MROWS (NB * TSEQ)   // 16384

typedef unsigned long long u64;

// ---- packed f32x2 helpers (sm_103a FFMA2 path) ----
__device__ __forceinline__ u64 pk2(float lo, float hi) {
    u64 d;
    asm("mov.b64 %0, {%1, %2};" : "=l"(d) : "f"(lo), "f"(hi));
    return d;
}
__device__ __forceinline__ void upk2(float& lo, float& hi, u64 v) {
    asm("mov.b64 {%0, %1}, %2;" : "=f"(lo), "=f"(hi) : "l"(v));
}
__device__ __forceinline__ void fma2(u64& d, u64 a, u64 b) {
    asm("fma.rn.f32x2 %0, %1, %2, %0;" : "+l"(d) : "l"(a), "l"(b));
}
__device__ __forceinline__ void mul2(u64& d, u64 a) {
    asm("mul.rn.f32x2 %0, %0, %1;" : "+l"(d) : "l"(a));
}

// Scratch for projected q, k, v  (12 MB total) — __device__ globals per alloc rules
__device__ float g_q[MROWS * HDIM];
__device__ float g_k[MROWS * HDIM];
__device__ float g_v[MROWS * HDIM];

// ---------------------------------------------------------------------------
// Projection: out[m][h] = sum_c x[m][c] * W[h][c]
// BM=128, BN=64, BK=32, 256 threads, 8x4 microtile, f32x2 packed over c-pairs.
// grid = (MROWS/128, 3); blockIdx.y selects (Wq->g_q, Wk->g_k, Wv->g_v)
// ---------------------------------------------------------------------------
#define PJ_STR 36   // 32 + 4 pad

__global__ __launch_bounds__(256) void proj_kernel(
    const float* __restrict__ x,
    const float* __restrict__ Wq,
    const float* __restrict__ Wk,
    const float* __restrict__ Wv)
{
    __shared__ float As[128 * PJ_STR];  // x tile [m][c]
    __shared__ float Bs[64 * PJ_STR];   // W tile [n][c]

    const int wsel = blockIdx.y;
    const float* __restrict__ W = (wsel == 0) ? Wq : ((wsel == 1) ? Wk : Wv);
    float* __restrict__ dst     = (wsel == 0) ? g_q : ((wsel == 1) ? g_k : g_v);

    const int m0 = blockIdx.x * 128;
    const int t  = threadIdx.x;
    const int tx = t & 15;
    const int ty = t >> 4;
    const int lrow = t >> 3;         // 0..31
    const int lc   = (t & 7) * 4;    // 0..28

    u64 acc[8][4] = {};              // packed (even c, odd c) partials

    for (int kb = 0; kb < CDIM; kb += 32) {
        #pragma unroll
        for (int p = 0; p < 4; p++) {     // As: 128 rows
            const int row = lrow + p * 32;
            *(float4*)(As + row * PJ_STR + lc) =
                *(const float4*)(x + (m0 + row) * CDIM + kb + lc);
        }
        #pragma unroll
        for (int p = 0; p < 2; p++) {     // Bs: 64 rows
            const int row = lrow + p * 32;
            *(float4*)(Bs + row * PJ_STR + lc) =
                *(const float4*)(W + row * CDIM + kb + lc);
        }
        __syncthreads();

        #pragma unroll
        for (int kk = 0; kk < 32; kk += 4) {
            ulonglong2 a2[8], b2[4];
            #pragma unroll
            for (int ii = 0; ii < 8; ii++)
                a2[ii] = *(const ulonglong2*)(As + (ty + 16 * ii) * PJ_STR + kk);
            #pragma unroll
            for (int jj = 0; jj < 4; jj++)
                b2[jj] = *(const ulonglong2*)(Bs + (tx + 16 * jj) * PJ_STR + kk);
            #pragma unroll
            for (int ii = 0; ii < 8; ii++)
                #pragma unroll
                for (int jj = 0; jj < 4; jj++) {
                    fma2(acc[ii][jj], a2[ii].x, b2[jj].x);
                    fma2(acc[ii][jj], a2[ii].y, b2[jj].y);
                }
        }
        __syncthreads();
    }

    #pragma unroll
    for (int ii = 0; ii < 8; ii++)
        #pragma unroll
        for (int jj = 0; jj < 4; jj++) {
            float lo, hi;
            upk2(lo, hi, acc[ii][jj]);
            dst[(m0 + ty + 16 * ii) * HDIM + (tx + 16 * jj)] = lo + hi;
        }
}

// ---------------------------------------------------------------------------
// Flash attention (fp32 via f32x2, causal). grid = (32, 4): each CTA does the
// complementary q-tile pair (63-bx, bx) -> uniform 65 iterations (R3 schedule,
// measured 315us in scalar form). 256 threads, 1 CTA/SM (104KB smem).
// K/V double-buffered via register prefetch; 2 barriers/iter.
// S GEMM packs the kk reduction dim; PV packs the output-col dim.
// P staged as St[j][ty*4+ii] (float4-readable, stride 68).
// ---------------------------------------------------------------------------
#define AT_STR  68
#define KV_BUF  (64 * AT_STR)
#define SM_QS   0
#define SM_KS   (64 * AT_STR)
#define SM_VS   (3 * 64 * AT_STR)
#define SM_ST   (5 * 64 * AT_STR)
#define SM_TOTF (6 * 64 * AT_STR)           // 26112 floats
#define ATTN_SMEM_BYTES (SM_TOTF * 4)       // 104448 bytes

__global__ __launch_bounds__(256) void attn_kernel(float* __restrict__ out)
{
    extern __shared__ float sm[];
    float* Qs = sm + SM_QS;
    float* Ks = sm + SM_KS;   // Ks + cur*KV_BUF
    float* Vs = sm + SM_VS;
    float* St = sm + SM_ST;

    const int t  = threadIdx.x;
    const int tx = t & 15;
    const int ty = t >> 4;
    const int bx = blockIdx.x;            // 0..31
    const int b  = blockIdx.y;
    const float NEGBIG = -1e30f;
    const float scale  = 0.125f;          // 64^-0.5

    const int lrow0 = t >> 4;
    const int lcol  = (t & 15) * 4;

    const float* __restrict__ kbase = g_k + b * TSEQ * HDIM;
    const float* __restrict__ vbase = g_v + b * TSEQ * HDIM;

    #pragma unroll 1
    for (int half = 0; half < 2; half++) {
        const int qb = (half == 0) ? (63 - bx) : bx;   // heavy tile first

        // ---- load Q tile (pre-scaled) + prologue K/V(0) into buf 0 ----
        {
            const float* __restrict__ qsrc = g_q + (b * TSEQ + qb * 64) * HDIM;
            #pragma unroll
            for (int p = 0; p < 4; p++) {
                const int row = lrow0 + p * 16;
                float4 q4 = *(const float4*)(qsrc + row * HDIM + lcol);
                q4.x *= scale; q4.y *= scale; q4.z *= scale; q4.w *= scale;
                *(float4*)(Qs + row * AT_STR + lcol) = q4;
                *(float4*)(Ks + row * AT_STR + lcol) =
                    *(const float4*)(kbase + row * HDIM + lcol);
                *(float4*)(Vs + row * AT_STR + lcol) =
                    *(const float4*)(vbase + row * HDIM + lcol);
            }
        }

        float m_i[4], l_i[4];
        #pragma unroll
        for (int ii = 0; ii < 4; ii++) { m_i[ii] = NEGBIG; l_i[ii] = 0.0f; }
        u64 o01[4] = {}, o23[4] = {};       // packed output cols (0,1) and (2,3)

        __syncthreads();                               // prologue barrier

        for (int jt = 0; jt <= qb; jt++) {
            const int cur = jt & 1;
            float* __restrict__ Kc = Ks + cur * KV_BUF;
            float* __restrict__ Vc = Vs + cur * KV_BUF;

            // ---- prefetch next K/V tile into registers ----
            float4 kpf[4], vpf[4];
            const bool pf = (jt < qb);
            if (pf) {
                const float* __restrict__ ksrc = kbase + (jt + 1) * 64 * HDIM;
                const float* __restrict__ vsrc = vbase + (jt + 1) * 64 * HDIM;
                #pragma unroll
                for (int p = 0; p < 4; p++) {
                    const int row = lrow0 + p * 16;
                    kpf[p] = *(const float4*)(ksrc + row * HDIM + lcol);
                    vpf[p] = *(const float4*)(vsrc + row * HDIM + lcol);
                }
            }

            // ---- S = (Q*scale) @ K^T : packed over kk pairs ----
            u64 sp[4][4] = {};
            #pragma unroll
            for (int kk = 0; kk < 64; kk += 4) {
                ulonglong2 a2[4], b2[4];
                #pragma unroll
                for (int ii = 0; ii < 4; ii++)
                    a2[ii] = *(const ulonglong2*)(Qs + (ty + 16 * ii) * AT_STR + kk);
                #pragma unroll
                for (int jj = 0; jj < 4; jj++)
                    b2[jj] = *(const ulonglong2*)(Kc + (tx + 16 * jj) * AT_STR + kk);
                #pragma unroll
                for (int ii = 0; ii < 4; ii++)
                    #pragma unroll
                    for (int jj = 0; jj < 4; jj++) {
                        fma2(sp[ii][jj], a2[ii].x, b2[jj].x);
                        fma2(sp[ii][jj], a2[ii].y, b2[jj].y);
                    }
            }
            // fold packed partials
            float s[4][4];
            #pragma unroll
            for (int ii = 0; ii < 4; ii++)
                #pragma unroll
                for (int jj = 0; jj < 4; jj++) {
                    float lo, hi;
                    upk2(lo, hi, sp[ii][jj]);
                    s[ii][jj] = lo + hi;
                }

            // causal mask on the diagonal tile
            if (jt == qb) {
                #pragma unroll
                for (int ii = 0; ii < 4; ii++)
                    #pragma unroll
                    for (int jj = 0; jj < 4; jj++)
                        if ((tx + 16 * jj) > (ty + 16 * ii)) s[ii][jj] = NEGBIG;
            }

            // ---- online softmax (register-resident, 16-lane shuffle trees) ----
            #pragma unroll
            for (int ii = 0; ii < 4; ii++) {
                float tm = fmaxf(fmaxf(s[ii][0], s[ii][1]),
                                 fmaxf(s[ii][2], s[ii][3]));
                #pragma unroll
                for (int w = 1; w < 16; w <<= 1)
                    tm = fmaxf(tm, __shfl_xor_sync(0xffffffffu, tm, w));
                const float mnew = fmaxf(m_i[ii], tm);
                const float alpha = __expf(m_i[ii] - mnew);
                m_i[ii] = mnew;

                float p0 = __expf(s[ii][0] - mnew);
                float p1 = __expf(s[ii][1] - mnew);
                float p2 = __expf(s[ii][2] - mnew);
                float p3 = __expf(s[ii][3] - mnew);
                float rs = (p0 + p1) + (p2 + p3);
                #pragma unroll
                for (int w = 1; w < 16; w <<= 1)
                    rs += __shfl_xor_sync(0xffffffffu, rs, w);
                l_i[ii] = l_i[ii] * alpha + rs;

                const u64 ad = pk2(alpha, alpha);
                mul2(o01[ii], ad);
                mul2(o23[ii], ad);

                const int pc = ty * 4 + ii;
                St[(tx +  0) * AT_STR + pc] = p0;
                St[(tx + 16) * AT_STR + pc] = p1;
                St[(tx + 32) * AT_STR + pc] = p2;
                St[(tx + 48) * AT_STR + pc] = p3;
            }
            __syncthreads();                           // barrier A: St ready

            // ---- O += P @ V : packed over output-col pairs ----
            #pragma unroll 8
            for (int j = 0; j < 64; j++) {
                const float4 pv = *(const float4*)(St + j * AT_STR + ty * 4);
                const ulonglong2 vv =
                    *(const ulonglong2*)(Vc + j * AT_STR + tx * 4);
                const float pa[4] = {pv.x, pv.y, pv.z, pv.w};
                #pragma unroll
                for (int ii = 0; ii < 4; ii++) {
                    const u64 pd = pk2(pa[ii], pa[ii]);
                    fma2(o01[ii], pd, vv.x);
                    fma2(o23[ii], pd, vv.y);
                }
            }

            // ---- stage prefetched K/V into the alternate buffer ----
            if (pf) {
                float* __restrict__ Kn = Ks + (1 - cur) * KV_BUF;
                float* __restrict__ Vn = Vs + (1 - cur) * KV_BUF;
                #pragma unroll
                for (int p = 0; p < 4; p++) {
                    const int row = lrow0 + p * 16;
                    *(float4*)(Kn + row * AT_STR + lcol) = kpf[p];
                    *(float4*)(Vn + row * AT_STR + lcol) = vpf[p];
                }
            }
            __syncthreads();                           // barrier B: bufs/St safe
        }

        // ---- epilogue: out = O / l ----
        #pragma unroll
        for (int ii = 0; ii < 4; ii++) {
            const int i     = ty + 16 * ii;
            const float inv = 1.0f / l_i[ii];
            float c0, c1, c2, c3;
            upk2(c0, c1, o01[ii]);
            upk2(c2, c3, o23[ii]);
            float4 ov;
            ov.x = c0 * inv; ov.y = c1 * inv;
            ov.z = c2 * inv; ov.w = c3 * inv;
            *(float4*)(out + (b * TSEQ + qb * 64 + i) * HDIM + tx * 4) = ov;
        }
    }
}

// ---------------------------------------------------------------------------
// kernel_launch — inputs (metadata order): x, mask(int32, unused), Wk, Wq, Wv
// ---------------------------------------------------------------------------
extern "C" void kernel_launch(void* const* d_in, const int* in_sizes, int n_in,
                              void* d_out, int out_size)
{
    const float* x  = (const float*)d_in[0];
    // d_in[1] = mask (int32) — causality is known; not read.
    const float* Wk = (const float*)d_in[2];
    const float* Wq = (const float*)d_in[3];
    const float* Wv = (const float*)d_in[4];
    float* out = (float*)d_out;

    // Host-side attribute set; not a stream op, safe under graph capture.
    cudaFuncSetAttribute(attn_kernel,
                         cudaFuncAttributeMaxDynamicSharedMemorySize,
                         ATTN_SMEM_BYTES);

    dim3 pgrid(MROWS / 128, 3);
    proj_kernel<<<pgrid, 256>>>(x, Wq, Wk, Wv);

    dim3 agrid(32, NB);   // paired q-tiles: uniform 65 iterations per CTA
    attn_kernel<<<agrid, 256, ATTN_SMEM_BYTES>>>(out);
}